// round 4
// baseline (speedup 1.0000x reference)
#include <cuda_runtime.h>
#include <math_constants.h>

#define BB 4096
#define PP 128
#define GG 128

#define SCX (8000.0f / 79.0f)
#define SCY (8000.0f / 79.0f)
#define SCZ (2000.0f / 19.0f)
#define BX (-4000.0f)
#define BY (-4000.0f)
#define BZ (0.0f)

#define DIST_THRESH_SQ (500.0f * 500.0f)
#define BBOX_THRESH 0.1f
#define EOFF 2.0e8f              // offset making e strictly positive
#define KEYMASK (~31)            // drop low 5 float bits, store q (q < 32)

// ---- packed f32x2 helpers (sm_103a) ----
__device__ __forceinline__ unsigned long long pack2(float lo, float hi) {
    unsigned long long r;
    asm("mov.b64 %0, {%1, %2};" : "=l"(r) : "f"(lo), "f"(hi));
    return r;
}
__device__ __forceinline__ void unpack2(unsigned long long v, float& lo, float& hi) {
    asm("mov.b64 {%0, %1}, %2;" : "=f"(lo), "=f"(hi) : "l"(v));
}
__device__ __forceinline__ unsigned long long fma2(unsigned long long a, unsigned long long b,
                                                   unsigned long long c) {
    unsigned long long r;
    asm("fma.rn.f32x2 %0, %1, %2, %3;" : "=l"(r) : "l"(a), "l"(b), "l"(c));
    return r;
}

__global__ __launch_bounds__(PP)
void proposal_layer_kernel(const int*   __restrict__ topk_index,      // [B,P,3]
                           const float* __restrict__ topk_confs,      // [B,P]
                           const float* __restrict__ match_bbox_preds,// [B,P,2]
                           const float* __restrict__ roots_3d,        // [B,G,3]
                           const float* __restrict__ gt_bbox,         // [B,G,2]
                           const int*   __restrict__ num_person,      // [B]
                           float*       __restrict__ out)             // [B,P,7]
{
    const int b = blockIdx.x;
    const int p = threadIdx.x;  // 0..127

    __shared__ __align__(16) float s_nx[GG];   // -rx
    __shared__ __align__(16) float s_ny[GG];   // -ry
    __shared__ __align__(16) float s_nz[GG];   // -rz
    __shared__ __align__(16) float s_h[GG];    // |r|^2/2 + EOFF
    __shared__ float2 s_bbox[GG];
    __shared__ float  s_out[PP * 7];

    {
        const float* r = roots_3d + ((size_t)b * GG + p) * 3;
        float rx = r[0], ry = r[1], rz = r[2];
        s_nx[p] = -rx;
        s_ny[p] = -ry;
        s_nz[p] = -rz;
        s_h[p]  = __fmaf_rn(0.5f, __fmaf_rn(rz, rz, __fmaf_rn(ry, ry, rx * rx)), EOFF);
        const float* gb = gt_bbox + ((size_t)b * GG + p) * 2;
        s_bbox[p] = make_float2(gb[0], gb[1]);
    }
    const int n = num_person[b];
    __syncthreads();

    const int* ti = topk_index + ((size_t)b * PP + p) * 3;
    const float cx = (float)ti[0] * SCX + BX;
    const float cy = (float)ti[1] * SCY + BY;
    const float cz = (float)ti[2] * SCZ + BZ;
    const float cc = __fmaf_rn(cz, cz, __fmaf_rn(cy, cy, cx * cx));

    const float conf = topk_confs[(size_t)b * PP + p];
    const float* mp = match_bbox_preds + ((size_t)b * PP + p) * 2;
    const float pb0 = mp[0];
    const float pb1 = mp[1];

    const unsigned long long cxx = pack2(cx, cx);
    const unsigned long long cyy = pack2(cy, cy);
    const unsigned long long czz = pack2(cz, cz);

    const ulonglong2* px = (const ulonglong2*)s_nx;
    const ulonglong2* py = (const ulonglong2*)s_ny;
    const ulonglong2* pz = (const ulonglong2*)s_nz;
    const ulonglong2* ph = (const ulonglong2*)s_h;

    // 4 key chains (residue mod 4); key = (float_bits(e+EOFF) & ~31) | q
    int bk0 = 0x7FFFFFFF, bk1 = 0x7FFFFFFF, bk2 = 0x7FFFFFFF, bk3 = 0x7FFFFFFF;

    const int nb = n >> 2;
    #pragma unroll 4
    for (int q = 0; q < nb; ++q) {
        ulonglong2 X = px[q];   // 4 LDS.128 broadcast
        ulonglong2 Y = py[q];
        ulonglong2 Z = pz[q];
        ulonglong2 H = ph[q];

        unsigned long long eA = fma2(cxx, X.x, fma2(cyy, Y.x, fma2(czz, Z.x, H.x)));
        unsigned long long eB = fma2(cxx, X.y, fma2(cyy, Y.y, fma2(czz, Z.y, H.y)));
        float s0, s1, s2, s3;
        unpack2(eA, s0, s1);
        unpack2(eB, s2, s3);

        int k0 = (__float_as_int(s0) & KEYMASK) | q;   // LOP3
        int k1 = (__float_as_int(s1) & KEYMASK) | q;
        int k2 = (__float_as_int(s2) & KEYMASK) | q;
        int k3 = (__float_as_int(s3) & KEYMASK) | q;
        bk0 = min(bk0, k0);                             // IMNMX (4-cyc chain)
        bk1 = min(bk1, k1);
        bk2 = min(bk2, k2);
        bk3 = min(bk3, k3);
    }

    // merge chains: masked value, strict < (ties inside 5-bit bucket accepted)
    int best_mv = bk0 & KEYMASK;
    int bi = ((bk0 & 31) << 2);
    { int mv = bk1 & KEYMASK; if (mv < best_mv) { best_mv = mv; bi = ((bk1 & 31) << 2) + 1; } }
    { int mv = bk2 & KEYMASK; if (mv < best_mv) { best_mv = mv; bi = ((bk2 & 31) << 2) + 2; } }
    { int mv = bk3 & KEYMASK; if (mv < best_mv) { best_mv = mv; bi = ((bk3 & 31) << 2) + 3; } }

    // scalar tail (g >= nb*4): same masked ordering, strict < keeps earlier g
    for (int g = (nb << 2); g < n; ++g) {
        float e = __fmaf_rn(cx, s_nx[g], __fmaf_rn(cy, s_ny[g], __fmaf_rn(cz, s_nz[g], s_h[g])));
        int mv = __float_as_int(e) & KEYMASK;
        if (mv < best_mv) { best_mv = mv; bi = g; }
    }

    // exact threshold recheck for chosen bi:
    // d2 <= 500^2  <=>  e+EOFF <= 0.5*(500^2 - cc) + EOFF
    const float e_best = __fmaf_rn(cx, s_nx[bi],
                        __fmaf_rn(cy, s_ny[bi],
                        __fmaf_rn(cz, s_nz[bi], s_h[bi])));
    const float thresh_e = __fmaf_rn(-0.5f, cc, 0.5f * DIST_THRESH_SQ + EOFF);
    const bool matched = !(e_best > thresh_e);
    const float p2g = matched ? (float)bi : -1.0f;

    float2 mb = s_bbox[bi];
    bool ow = matched && ((pb0 < mb.x - BBOX_THRESH) || (pb1 < mb.y - BBOX_THRESH));
    const float o5 = ow ? mb.x : pb0;
    const float o6 = ow ? mb.y : pb1;

    // stage [P,7] tile (stride 7 -> conflict-free), then coalesced store
    float* so = s_out + p * 7;
    so[0] = cx; so[1] = cy; so[2] = cz;
    so[3] = p2g; so[4] = conf;
    so[5] = o5;  so[6] = o6;
    __syncthreads();

    float* ob = out + (size_t)b * (PP * 7);
    #pragma unroll
    for (int i = p; i < PP * 7; i += PP)
        ob[i] = s_out[i];
}

extern "C" void kernel_launch(void* const* d_in, const int* in_sizes, int n_in,
                              void* d_out, int out_size)
{
    const int*   topk_index       = (const int*)  d_in[0];
    const float* topk_confs       = (const float*)d_in[1];
    const float* match_bbox_preds = (const float*)d_in[2];
    const float* roots_3d         = (const float*)d_in[3];
    const float* gt_bbox          = (const float*)d_in[4];
    const int*   num_person       = (const int*)  d_in[5];
    float* out = (float*)d_out;

    proposal_layer_kernel<<<BB, PP>>>(topk_index, topk_confs, match_bbox_preds,
                                      roots_3d, gt_bbox, num_person, out);
}

// round 5
// speedup vs baseline: 1.0120x; 1.0120x over previous
#include <cuda_runtime.h>
#include <math_constants.h>

#define BB 4096
#define PP 128
#define GG 128

#define SCX (8000.0f / 79.0f)
#define SCY (8000.0f / 79.0f)
#define SCZ (2000.0f / 19.0f)
#define BX (-4000.0f)
#define BY (-4000.0f)
#define BZ (0.0f)

#define DIST_THRESH_SQ (500.0f * 500.0f)
#define BBOX_THRESH 0.1f
#define EOFF 2.0e8f              // offset making e strictly positive
#define KEYMASK (~31)            // drop low 5 float bits, store q (q < 32)

// ---- packed f32x2 helpers (sm_103a) ----
__device__ __forceinline__ unsigned long long pack2(float lo, float hi) {
    unsigned long long r;
    asm("mov.b64 %0, {%1, %2};" : "=l"(r) : "f"(lo), "f"(hi));
    return r;
}
__device__ __forceinline__ void unpack2(unsigned long long v, float& lo, float& hi) {
    asm("mov.b64 {%0, %1}, %2;" : "=f"(lo), "=f"(hi) : "l"(v));
}
__device__ __forceinline__ unsigned long long fma2(unsigned long long a, unsigned long long b,
                                                   unsigned long long c) {
    unsigned long long r;
    asm("fma.rn.f32x2 %0, %1, %2, %3;" : "=l"(r) : "l"(a), "l"(b), "l"(c));
    return r;
}

__global__ __launch_bounds__(128, 10)
void proposal_layer_kernel(const int*   __restrict__ topk_index,      // [B,P,3]
                           const float* __restrict__ topk_confs,      // [B,P]
                           const float* __restrict__ match_bbox_preds,// [B,P,2]
                           const float* __restrict__ roots_3d,        // [B,G,3]
                           const float* __restrict__ gt_bbox,         // [B,G,2]
                           const int*   __restrict__ num_person,      // [B]
                           float*       __restrict__ out)             // [B,P,7]
{
    const int t   = threadIdx.x;
    const int grp = t >> 6;                 // 0/1: which batch of this CTA
    const int u   = t & 63;                 // lane within group
    const int b   = blockIdx.x * 2 + grp;   // batch id (warps never straddle groups)

    __shared__ __align__(16) float s_nx[2][GG];   // -rx
    __shared__ __align__(16) float s_ny[2][GG];   // -ry
    __shared__ __align__(16) float s_nz[2][GG];   // -rz
    __shared__ __align__(16) float s_h [2][GG];   // |r|^2/2 + EOFF
    __shared__ float2 s_bbox[2][GG];
    __shared__ float  s_out[2][PP * 7];

    // stage 2 g-entries per thread for this group's batch
    #pragma unroll
    for (int k = 0; k < 2; ++k) {
        const int g = u + (k << 6);
        const float* r = roots_3d + ((size_t)b * GG + g) * 3;
        float rx = r[0], ry = r[1], rz = r[2];
        s_nx[grp][g] = -rx;
        s_ny[grp][g] = -ry;
        s_nz[grp][g] = -rz;
        s_h [grp][g] = __fmaf_rn(0.5f, __fmaf_rn(rz, rz, __fmaf_rn(ry, ry, rx * rx)), EOFF);
        const float* gb = gt_bbox + ((size_t)b * GG + g) * 2;
        s_bbox[grp][g] = make_float2(gb[0], gb[1]);
    }
    const int n = num_person[b];            // uniform within group
    __syncthreads();

    // per-proposal setup: this thread owns proposals u and u+64 of batch b
    unsigned long long cxx[2], cyy[2], czz[2];
    float cc[2], conf[2], pb0[2], pb1[2];
    int bk[2][4];
    #pragma unroll
    for (int k = 0; k < 2; ++k) {
        const int p = u + (k << 6);
        const int* ti = topk_index + ((size_t)b * PP + p) * 3;
        float cx = (float)ti[0] * SCX + BX;
        float cy = (float)ti[1] * SCY + BY;
        float cz = (float)ti[2] * SCZ + BZ;
        cc[k]  = __fmaf_rn(cz, cz, __fmaf_rn(cy, cy, cx * cx));
        cxx[k] = pack2(cx, cx);
        cyy[k] = pack2(cy, cy);
        czz[k] = pack2(cz, cz);
        bk[k][0] = bk[k][1] = bk[k][2] = bk[k][3] = 0x7FFFFFFF;
        conf[k] = topk_confs[(size_t)b * PP + p];
        const float* mp = match_bbox_preds + ((size_t)b * PP + p) * 2;
        pb0[k] = mp[0];
        pb1[k] = mp[1];
    }

    const ulonglong2* px = (const ulonglong2*)s_nx[grp];
    const ulonglong2* py = (const ulonglong2*)s_ny[grp];
    const ulonglong2* pz = (const ulonglong2*)s_nz[grp];
    const ulonglong2* ph = (const ulonglong2*)s_h [grp];

    const int nb = n >> 2;
    #pragma unroll 2
    for (int q = 0; q < nb; ++q) {
        ulonglong2 X = px[q];   // 4 LDS.128 broadcast feed 8 (p,g) pairs
        ulonglong2 Y = py[q];
        ulonglong2 Z = pz[q];
        ulonglong2 H = ph[q];

        #pragma unroll
        for (int k = 0; k < 2; ++k) {
            unsigned long long eA =
                fma2(cxx[k], X.x, fma2(cyy[k], Y.x, fma2(czz[k], Z.x, H.x)));
            unsigned long long eB =
                fma2(cxx[k], X.y, fma2(cyy[k], Y.y, fma2(czz[k], Z.y, H.y)));
            float s0, s1, s2, s3;
            unpack2(eA, s0, s1);
            unpack2(eB, s2, s3);
            bk[k][0] = min(bk[k][0], (__float_as_int(s0) & KEYMASK) | q);
            bk[k][1] = min(bk[k][1], (__float_as_int(s1) & KEYMASK) | q);
            bk[k][2] = min(bk[k][2], (__float_as_int(s2) & KEYMASK) | q);
            bk[k][3] = min(bk[k][3], (__float_as_int(s3) & KEYMASK) | q);
        }
    }

    #pragma unroll
    for (int k = 0; k < 2; ++k) {
        float cx, cxd, cy, cyd, cz, czd;
        unpack2(cxx[k], cx, cxd);
        unpack2(cyy[k], cy, cyd);
        unpack2(czz[k], cz, czd);

        // merge 4 residue chains (masked value, strict <)
        int best_mv = bk[k][0] & KEYMASK;
        int bi = ((bk[k][0] & 31) << 2);
        { int mv = bk[k][1] & KEYMASK; if (mv < best_mv) { best_mv = mv; bi = ((bk[k][1] & 31) << 2) + 1; } }
        { int mv = bk[k][2] & KEYMASK; if (mv < best_mv) { best_mv = mv; bi = ((bk[k][2] & 31) << 2) + 2; } }
        { int mv = bk[k][3] & KEYMASK; if (mv < best_mv) { best_mv = mv; bi = ((bk[k][3] & 31) << 2) + 3; } }

        // scalar tail (g >= nb*4): same masked ordering, strict < keeps earlier g
        for (int g = (nb << 2); g < n; ++g) {
            float e = __fmaf_rn(cx, s_nx[grp][g],
                     __fmaf_rn(cy, s_ny[grp][g],
                     __fmaf_rn(cz, s_nz[grp][g], s_h[grp][g])));
            int mv = __float_as_int(e) & KEYMASK;
            if (mv < best_mv) { best_mv = mv; bi = g; }
        }

        // exact threshold recheck for chosen bi
        const float e_best = __fmaf_rn(cx, s_nx[grp][bi],
                            __fmaf_rn(cy, s_ny[grp][bi],
                            __fmaf_rn(cz, s_nz[grp][bi], s_h[grp][bi])));
        const float thresh_e = __fmaf_rn(-0.5f, cc[k], 0.5f * DIST_THRESH_SQ + EOFF);
        const bool matched = !(e_best > thresh_e);
        const float p2g = matched ? (float)bi : -1.0f;

        float2 mb = s_bbox[grp][bi];
        bool ow = matched && ((pb0[k] < mb.x - BBOX_THRESH) || (pb1[k] < mb.y - BBOX_THRESH));
        const float o5 = ow ? mb.x : pb0[k];
        const float o6 = ow ? mb.y : pb1[k];

        const int p = u + (k << 6);
        float* so = s_out[grp] + p * 7;  // stride 7 -> conflict-free
        so[0] = cx; so[1] = cy; so[2] = cz;
        so[3] = p2g; so[4] = conf[k];
        so[5] = o5;  so[6] = o6;
    }
    __syncthreads();

    // coalesced store: each 64-thread group writes its batch's 896 floats
    float* ob = out + (size_t)b * (PP * 7);
    #pragma unroll
    for (int i = u; i < PP * 7; i += 64)
        ob[i] = s_out[grp][i];
}

extern "C" void kernel_launch(void* const* d_in, const int* in_sizes, int n_in,
                              void* d_out, int out_size)
{
    const int*   topk_index       = (const int*)  d_in[0];
    const float* topk_confs       = (const float*)d_in[1];
    const float* match_bbox_preds = (const float*)d_in[2];
    const float* roots_3d         = (const float*)d_in[3];
    const float* gt_bbox          = (const float*)d_in[4];
    const int*   num_person       = (const int*)  d_in[5];
    float* out = (float*)d_out;

    proposal_layer_kernel<<<BB / 2, 128>>>(topk_index, topk_confs, match_bbox_preds,
                                           roots_3d, gt_bbox, num_person, out);
}